// round 10
// baseline (speedup 1.0000x reference)
#include <cuda_runtime.h>
#include <cfloat>

#define SPATIAL_SCALE 0.0625f
#define CC 256
#define HH 64
#define WW 64
#define HW 4096
#define KK 128
#define PH 7
#define PW 7
#define NBIN 49

// 8MB NHWC scratch: xt[b][h][w][c], float4-aligned
__device__ __align__(16) float g_xt[2 * HW * CC];

// ---------------- Kernel A: NCHW -> NHWC transpose ----------------
// Tile: 32c x 64hw. Grid (64, 8, 2) = 1024 blocks, 256 threads.
__global__ __launch_bounds__(256) void transpose_kernel(const float* __restrict__ x) {
    __shared__ float tile[32][65];
    const int b   = blockIdx.z;
    const int hw0 = blockIdx.x * 64;
    const int c0  = blockIdx.y * 32;
    const int t   = threadIdx.x;

    // Load: 2 float4 per thread along hw
    const int q  = t & 15;           // hw quad 0..15
    const int cL = t >> 4;           // 0..15
#pragma unroll
    for (int j = 0; j < 2; ++j) {
        const int c = cL + j * 16;
        const float4 v = *reinterpret_cast<const float4*>(
            x + ((long)(b * CC + c0 + c)) * HW + hw0 + q * 4);
        tile[c][q * 4 + 0] = v.x;
        tile[c][q * 4 + 1] = v.y;
        tile[c][q * 4 + 2] = v.z;
        tile[c][q * 4 + 3] = v.w;
    }
    __syncthreads();

    // Store: 2 float4 per thread along c
    const int cq = t & 7;            // c quad 0..7
    const int h0 = t >> 3;           // 0..31
#pragma unroll
    for (int j = 0; j < 2; ++j) {
        const int hh = h0 + j * 32;
        float4 v;
        v.x = tile[cq * 4 + 0][hh];
        v.y = tile[cq * 4 + 1][hh];
        v.z = tile[cq * 4 + 2][hh];
        v.w = tile[cq * 4 + 3][hh];
        *reinterpret_cast<float4*>(
            g_xt + ((long)(b * HW + hw0 + hh)) * CC + c0 + cq * 4) = v;
    }
}

__device__ __forceinline__ float4 f4max(float4 a, float4 b) {
    a.x = fmaxf(a.x, b.x);
    a.y = fmaxf(a.y, b.y);
    a.z = fmaxf(a.z, b.z);
    a.w = fmaxf(a.w, b.w);
    return a;
}

// ---------------- Kernel B: pool. Block = (k, c-chunk128, ph). 448 threads. ----------------
// Warp = (pw, row-half): one bin x 128 channels via LDG.128, rows split 2 ways.
__global__ __launch_bounds__(448) void roipool_kernel(
        const float* __restrict__ rois,
        float* __restrict__ out) {
    __shared__ float res[2][128 * 8];   // [half][c-local * 8 + pw]

    const int bx  = blockIdx.x;
    const int k   = bx / 14;            // 128 rois
    const int rem = bx - k * 14;
    const int c0  = (rem / 7) << 7;     // 0 or 128
    const int ph  = rem % 7;

    const int t    = threadIdx.x;       // 0..447
    const int wi   = t >> 5;            // 0..13
    const int pw   = wi % 7;            // warp-uniform
    const int half = wi / 7;            // 0 or 1
    const int cq   = t & 31;            // channel quad

    // ---- ROI geometry (bit-exact, verbatim) ----
    const float* r = rois + k * 5;
    const int b  = (int)__ldg(&r[0]);
    const int x1 = (int)rintf(__ldg(&r[1]) * SPATIAL_SCALE);
    const int y1 = (int)rintf(__ldg(&r[2]) * SPATIAL_SCALE);
    const int x2 = (int)rintf(__ldg(&r[3]) * SPATIAL_SCALE);
    const int y2 = (int)rintf(__ldg(&r[4]) * SPATIAL_SCALE);

    const int roi_w = max(x2 - x1 + 1, 1);
    const int roi_h = max(y2 - y1 + 1, 1);

    const float INV7 = __uint_as_float(0x3E124925u);  // fl(1/7): XLA recip-mul
    const float bw = __fmul_rn((float)roi_w, INV7);
    const float bh = __fmul_rn((float)roi_h, INV7);

    int hs = (int)floorf(__fmul_rn((float)ph, bh)) + y1;
    int he = (int)ceilf(__fmul_rn((float)(ph + 1), bh)) + y1;
    int ws = (int)floorf(__fmul_rn((float)pw, bw)) + x1;
    int we = (int)ceilf(__fmul_rn((float)(pw + 1), bw)) + x1;
    hs = min(max(hs, 0), HH);
    he = min(max(he, 0), HH);
    ws = min(max(ws, 0), WW);
    we = min(max(we, 0), WW);

    float4 m;
    if (hs >= he || ws >= we) {
        // Empty bin: both halves deposit 0 -> combined max is 0 (exact).
        m = make_float4(0.f, 0.f, 0.f, 0.f);
    } else {
        float4 m0 = make_float4(-FLT_MAX, -FLT_MAX, -FLT_MAX, -FLT_MAX);
        float4 m1 = m0;
        const int n = we - ws;
        const float* base = g_xt + (long)b * HW * CC + c0 + cq * 4;
        for (int h = hs + half; h < he; h += 2) {
            const float* p = base + (long)((h << 6) + ws) * CC;
            int w = 0;
            for (; w + 1 < n; w += 2) {
                m0 = f4max(m0, *reinterpret_cast<const float4*>(p + (long)w * CC));
                m1 = f4max(m1, *reinterpret_cast<const float4*>(p + (long)(w + 1) * CC));
            }
            if (w < n)
                m0 = f4max(m0, *reinterpret_cast<const float4*>(p + (long)w * CC));
        }
        m = f4max(m0, m1);   // max reordering is exact
    }
    res[half][(cq * 4 + 0) * 8 + pw] = m.x;
    res[half][(cq * 4 + 1) * 8 + pw] = m.y;
    res[half][(cq * 4 + 2) * 8 + pw] = m.z;
    res[half][(cq * 4 + 3) * 8 + pw] = m.w;
    __syncthreads();

    // Combine halves + store: 896 outputs = 128 c x 7 pw
    float* ob = out + ((long)(k * CC + c0)) * NBIN + ph * PW;
#pragma unroll
    for (int i = 0; i < 2; ++i) {
        const int j = t + i * 448;      // 0..895
        const int c = j / 7;
        const int p = j - c * 7;
        ob[(long)c * NBIN + p] = fmaxf(res[0][c * 8 + p], res[1][c * 8 + p]);
    }
}

extern "C" void kernel_launch(void* const* d_in, const int* in_sizes, int n_in,
                              void* d_out, int out_size) {
    const float* x    = (const float*)d_in[0];
    const float* rois = (const float*)d_in[1];
    if (n_in >= 2 && in_sizes[0] == KK * 5) {
        x    = (const float*)d_in[1];
        rois = (const float*)d_in[0];
    }
    float* out = (float*)d_out;

    dim3 gA(HW / 64, CC / 32, 2);    // 64 x 8 x 2 = 1024 blocks
    transpose_kernel<<<gA, 256>>>(x);

    roipool_kernel<<<KK * 2 * PH, 448>>>(rois, out);  // 1792 blocks
}

// round 11
// speedup vs baseline: 1.5203x; 1.5203x over previous
#include <cuda_runtime.h>
#include <cfloat>

#define SPATIAL_SCALE 0.0625f
#define CC 256
#define HH 64
#define WW 64
#define HW 4096
#define KK 128
#define PH 7
#define PW 7
#define NBIN 49

// 8MB NHWC scratch: xt[b][h][w][c], float4-aligned
__device__ __align__(16) float g_xt[2 * HW * CC];

// ---------------- Kernel A: NCHW -> NHWC transpose ----------------
// Tile: 32c x 64hw. Grid (64, 8, 2) = 1024 blocks, 256 threads. (measured ~2.7us)
__global__ __launch_bounds__(256) void transpose_kernel(const float* __restrict__ x) {
    __shared__ float tile[32][65];
    const int b   = blockIdx.z;
    const int hw0 = blockIdx.x * 64;
    const int c0  = blockIdx.y * 32;
    const int t   = threadIdx.x;

    const int q  = t & 15;
    const int cL = t >> 4;
#pragma unroll
    for (int j = 0; j < 2; ++j) {
        const int c = cL + j * 16;
        const float4 v = *reinterpret_cast<const float4*>(
            x + ((long)(b * CC + c0 + c)) * HW + hw0 + q * 4);
        tile[c][q * 4 + 0] = v.x;
        tile[c][q * 4 + 1] = v.y;
        tile[c][q * 4 + 2] = v.z;
        tile[c][q * 4 + 3] = v.w;
    }
    __syncthreads();

    const int cq = t & 7;
    const int h0 = t >> 3;
#pragma unroll
    for (int j = 0; j < 2; ++j) {
        const int hh = h0 + j * 32;
        float4 v;
        v.x = tile[cq * 4 + 0][hh];
        v.y = tile[cq * 4 + 1][hh];
        v.z = tile[cq * 4 + 2][hh];
        v.w = tile[cq * 4 + 3][hh];
        *reinterpret_cast<float4*>(
            g_xt + ((long)(b * HW + hw0 + hh)) * CC + c0 + cq * 4) = v;
    }
}

__device__ __forceinline__ float4 f4max(float4 a, float4 b) {
    a.x = fmaxf(a.x, b.x);
    a.y = fmaxf(a.y, b.y);
    a.z = fmaxf(a.z, b.z);
    a.w = fmaxf(a.w, b.w);
    return a;
}

// ---------------- Kernel B: pool. Block = (k, c-chunk128, ph). 224 threads. ----------------
// Warp = one (ph,pw) bin x 128 channels via LDG.128. Row-pair unroll -> 4 loads in flight.
__global__ __launch_bounds__(224) void roipool_kernel(
        const float* __restrict__ rois,
        float* __restrict__ out) {
    __shared__ float4 res4[PH][33];     // [pw][c-quad], lanes consecutive -> conflict-free

    const int bx  = blockIdx.x;
    const int k   = bx / 14;
    const int rem = bx - k * 14;
    const int c0  = (rem / 7) << 7;     // 0 or 128
    const int ph  = rem % 7;

    const int t  = threadIdx.x;         // 0..223
    const int pw = t >> 5;              // warp-uniform
    const int cq = t & 31;              // channel quad

    // ---- ROI geometry (bit-exact, verbatim) ----
    const float* r = rois + k * 5;
    const int b  = (int)__ldg(&r[0]);
    const int x1 = (int)rintf(__ldg(&r[1]) * SPATIAL_SCALE);
    const int y1 = (int)rintf(__ldg(&r[2]) * SPATIAL_SCALE);
    const int x2 = (int)rintf(__ldg(&r[3]) * SPATIAL_SCALE);
    const int y2 = (int)rintf(__ldg(&r[4]) * SPATIAL_SCALE);

    const int roi_w = max(x2 - x1 + 1, 1);
    const int roi_h = max(y2 - y1 + 1, 1);

    const float INV7 = __uint_as_float(0x3E124925u);  // fl(1/7): XLA recip-mul
    const float bw = __fmul_rn((float)roi_w, INV7);
    const float bh = __fmul_rn((float)roi_h, INV7);

    int hs = (int)floorf(__fmul_rn((float)ph, bh)) + y1;
    int he = (int)ceilf(__fmul_rn((float)(ph + 1), bh)) + y1;
    int ws = (int)floorf(__fmul_rn((float)pw, bw)) + x1;
    int we = (int)ceilf(__fmul_rn((float)(pw + 1), bw)) + x1;
    hs = min(max(hs, 0), HH);
    he = min(max(he, 0), HH);
    ws = min(max(ws, 0), WW);
    we = min(max(we, 0), WW);

    float4 m;
    if (hs >= he || ws >= we) {
        m = make_float4(0.f, 0.f, 0.f, 0.f);
    } else {
        float4 m0 = make_float4(-FLT_MAX, -FLT_MAX, -FLT_MAX, -FLT_MAX);
        float4 m1 = m0, m2 = m0, m3 = m0;
        const int n = we - ws;
        const float* base = g_xt + (long)b * HW * CC + c0 + cq * 4;
        int h = hs;
        // Row pairs: 4 independent LDG.128 per inner iteration
        for (; h + 1 < he; h += 2) {
            const float* p0 = base + (long)((h << 6) + ws) * CC;
            const float* p1 = p0 + (long)(WW * CC);
            int w = 0;
            for (; w + 1 < n; w += 2) {
                m0 = f4max(m0, *reinterpret_cast<const float4*>(p0 + (long)w * CC));
                m1 = f4max(m1, *reinterpret_cast<const float4*>(p0 + (long)(w + 1) * CC));
                m2 = f4max(m2, *reinterpret_cast<const float4*>(p1 + (long)w * CC));
                m3 = f4max(m3, *reinterpret_cast<const float4*>(p1 + (long)(w + 1) * CC));
            }
            if (w < n) {
                m0 = f4max(m0, *reinterpret_cast<const float4*>(p0 + (long)w * CC));
                m2 = f4max(m2, *reinterpret_cast<const float4*>(p1 + (long)w * CC));
            }
        }
        if (h < he) {   // trailing odd row
            const float* p0 = base + (long)((h << 6) + ws) * CC;
            int w = 0;
            for (; w + 1 < n; w += 2) {
                m0 = f4max(m0, *reinterpret_cast<const float4*>(p0 + (long)w * CC));
                m1 = f4max(m1, *reinterpret_cast<const float4*>(p0 + (long)(w + 1) * CC));
            }
            if (w < n)
                m0 = f4max(m0, *reinterpret_cast<const float4*>(p0 + (long)w * CC));
        }
        m = f4max(f4max(m0, m1), f4max(m2, m3));   // max reordering is exact
    }
    res4[pw][cq] = m;      // conflict-free float4 store
    __syncthreads();

    // Store: block owns out[(k*256+c0+c)*49 + ph*7 + p], c in [0,128), p in [0,7)
    const float* resf = reinterpret_cast<const float*>(res4);   // idx = pw*132 + c
    float* ob = out + ((long)(k * CC + c0)) * NBIN + ph * PW;
#pragma unroll
    for (int i = 0; i < 4; ++i) {
        const int j = t + i * 224;      // 0..895
        const int c = j / 7;
        const int p = j - c * 7;
        ob[(long)c * NBIN + p] = resf[p * 132 + c];
    }
}

extern "C" void kernel_launch(void* const* d_in, const int* in_sizes, int n_in,
                              void* d_out, int out_size) {
    const float* x    = (const float*)d_in[0];
    const float* rois = (const float*)d_in[1];
    if (n_in >= 2 && in_sizes[0] == KK * 5) {
        x    = (const float*)d_in[1];
        rois = (const float*)d_in[0];
    }
    float* out = (float*)d_out;

    dim3 gA(HW / 64, CC / 32, 2);    // 1024 blocks
    transpose_kernel<<<gA, 256>>>(x);

    roipool_kernel<<<KK * 2 * PH, 224>>>(rois, out);  // 1792 blocks
}

// round 12
// speedup vs baseline: 1.5873x; 1.0441x over previous
#include <cuda_runtime.h>
#include <cfloat>

#define SPATIAL_SCALE 0.0625f
#define CC 256
#define HH 64
#define WW 64
#define HW 4096
#define KK 128
#define PH 7
#define PW 7
#define NBIN 49

// 8MB NHWC scratch: xt[b][h][w][c], float4-aligned
__device__ __align__(16) float g_xt[2 * HW * CC];

// ---------------- Kernel A: NCHW -> NHWC transpose ----------------
// Tile: 32c x 32hw. Grid (128, 8, 2) = 2048 blocks, 256 threads.
__global__ __launch_bounds__(256) void transpose_kernel(const float* __restrict__ x) {
    __shared__ float tile[32][33];
    const int b   = blockIdx.z;
    const int hw0 = blockIdx.x * 32;
    const int c0  = blockIdx.y * 32;
    const int t   = threadIdx.x;

    // Load: 1 float4 per thread along hw
    {
        const int q = t & 7;         // hw quad 0..7
        const int c = t >> 3;        // 0..31
        const float4 v = *reinterpret_cast<const float4*>(
            x + ((long)(b * CC + c0 + c)) * HW + hw0 + q * 4);
        tile[c][q * 4 + 0] = v.x;
        tile[c][q * 4 + 1] = v.y;
        tile[c][q * 4 + 2] = v.z;
        tile[c][q * 4 + 3] = v.w;
    }
    __syncthreads();

    // Store: 1 float4 per thread along c
    {
        const int cq = t & 7;        // c quad 0..7
        const int hh = t >> 3;       // 0..31
        float4 v;
        v.x = tile[cq * 4 + 0][hh];
        v.y = tile[cq * 4 + 1][hh];
        v.z = tile[cq * 4 + 2][hh];
        v.w = tile[cq * 4 + 3][hh];
        *reinterpret_cast<float4*>(
            g_xt + ((long)(b * HW + hw0 + hh)) * CC + c0 + cq * 4) = v;
    }
}

__device__ __forceinline__ float4 f4max(float4 a, float4 b) {
    a.x = fmaxf(a.x, b.x);
    a.y = fmaxf(a.y, b.y);
    a.z = fmaxf(a.z, b.z);
    a.w = fmaxf(a.w, b.w);
    return a;
}

// Strides in float4 units: w+1 -> +64, h+1 -> +4096
#define SW4 64
#define SH4 4096

// ---------------- Kernel B: pool. Block = (k, c-chunk128, ph). 224 threads. ----------------
// Warp = one (ph,pw) bin x 128 channels via LDG.128 with IMMEDIATE offsets.
__global__ __launch_bounds__(224) void roipool_kernel(
        const float* __restrict__ rois,
        float* __restrict__ out) {
    __shared__ float4 res4[PH][33];     // [pw][c-quad], conflict-free

    const int bx  = blockIdx.x;
    const int k   = bx / 14;
    const int rem = bx - k * 14;
    const int c0  = (rem / 7) << 7;     // 0 or 128
    const int ph  = rem % 7;

    const int t  = threadIdx.x;         // 0..223
    const int pw = t >> 5;              // warp-uniform
    const int cq = t & 31;              // channel quad

    // ---- ROI geometry (bit-exact, verbatim) ----
    const float* r = rois + k * 5;
    const int b  = (int)__ldg(&r[0]);
    const int x1 = (int)rintf(__ldg(&r[1]) * SPATIAL_SCALE);
    const int y1 = (int)rintf(__ldg(&r[2]) * SPATIAL_SCALE);
    const int x2 = (int)rintf(__ldg(&r[3]) * SPATIAL_SCALE);
    const int y2 = (int)rintf(__ldg(&r[4]) * SPATIAL_SCALE);

    const int roi_w = max(x2 - x1 + 1, 1);
    const int roi_h = max(y2 - y1 + 1, 1);

    const float INV7 = __uint_as_float(0x3E124925u);  // fl(1/7): XLA recip-mul
    const float bw = __fmul_rn((float)roi_w, INV7);
    const float bh = __fmul_rn((float)roi_h, INV7);

    int hs = (int)floorf(__fmul_rn((float)ph, bh)) + y1;
    int he = (int)ceilf(__fmul_rn((float)(ph + 1), bh)) + y1;
    int ws = (int)floorf(__fmul_rn((float)pw, bw)) + x1;
    int we = (int)ceilf(__fmul_rn((float)(pw + 1), bw)) + x1;
    hs = min(max(hs, 0), HH);
    he = min(max(he, 0), HH);
    ws = min(max(ws, 0), WW);
    we = min(max(we, 0), WW);

    float4 m;
    if (hs >= he || ws >= we) {
        m = make_float4(0.f, 0.f, 0.f, 0.f);
    } else {
        float4 m0 = make_float4(-FLT_MAX, -FLT_MAX, -FLT_MAX, -FLT_MAX);
        float4 m1 = m0, m2 = m0, m3 = m0;
        const int n = we - ws;
        // float4-unit base pointer for (hs, ws, c0+cq*4)
        const float4* p = reinterpret_cast<const float4*>(g_xt)
                        + (b * HW * (CC / 4)) + ((hs << 6) + ws) * SW4 + (c0 >> 2) + cq;
        int rows = he - hs;
        // Row-pair loop: 4 LDG.128 with immediate offsets per inner iteration
        for (; rows >= 2; rows -= 2) {
            const float4* q = p;
            int w = n;
            for (; w >= 2; w -= 2) {
                m0 = f4max(m0, q[0]);
                m1 = f4max(m1, q[SW4]);
                m2 = f4max(m2, q[SH4]);
                m3 = f4max(m3, q[SH4 + SW4]);
                q += 2 * SW4;
            }
            if (w) {
                m0 = f4max(m0, q[0]);
                m2 = f4max(m2, q[SH4]);
            }
            p += 2 * SH4;
        }
        if (rows) {
            const float4* q = p;
            int w = n;
            for (; w >= 2; w -= 2) {
                m0 = f4max(m0, q[0]);
                m1 = f4max(m1, q[SW4]);
                q += 2 * SW4;
            }
            if (w) m0 = f4max(m0, q[0]);
        }
        m = f4max(f4max(m0, m1), f4max(m2, m3));   // max reordering is exact
    }
    res4[pw][cq] = m;
    __syncthreads();

    // Store: block owns out[(k*256+c0+c)*49 + ph*7 + p], c in [0,128), p in [0,7)
    const float* resf = reinterpret_cast<const float*>(res4);   // idx = pw*132 + c
    float* ob = out + ((long)(k * CC + c0)) * NBIN + ph * PW;
#pragma unroll
    for (int i = 0; i < 4; ++i) {
        const int j = t + i * 224;      // 0..895
        const int c = j / 7;
        const int p = j - c * 7;
        ob[(long)c * NBIN + p] = resf[p * 132 + c];
    }
}

extern "C" void kernel_launch(void* const* d_in, const int* in_sizes, int n_in,
                              void* d_out, int out_size) {
    const float* x    = (const float*)d_in[0];
    const float* rois = (const float*)d_in[1];
    if (n_in >= 2 && in_sizes[0] == KK * 5) {
        x    = (const float*)d_in[1];
        rois = (const float*)d_in[0];
    }
    float* out = (float*)d_out;

    dim3 gA(HW / 32, CC / 32, 2);    // 2048 blocks
    transpose_kernel<<<gA, 256>>>(x);

    roipool_kernel<<<KK * 2 * PH, 224>>>(rois, out);  // 1792 blocks
}